// round 4
// baseline (speedup 1.0000x reference)
#include <cuda_runtime.h>
#include <math.h>

// Problem constants (fixed by setup_inputs: B=4, N=2048, D_MODEL=512)
#define N_PTS   2048
#define N_WAVES 256              // D_MODEL / 2
#define T       16               // tile rows
#define NT      (N_PTS / T)      // 128 tiles
#define W       8                // j-tiles per strip
#define NSTRIPS (NT / W)         // 16
#define F_MUFU  14               // ii < F_MUFU -> MUFU path, rest -> FMA poly path

__device__ __forceinline__ void red_add_v2(float* p, float x, float y) {
    asm volatile("red.global.add.v2.f32 [%0], {%1, %2};"
                 :: "l"(p), "f"(x), "f"(y) : "memory");
}

// FMA-pipe sincos: range-reduce to [-pi/4, pi/4], Taylor polys, quadrant fixup
// on ALU pipe. Valid for ph in [0, ~1e4]. Error ~< 1e-6 abs.
__device__ __forceinline__ void sincos_poly(float ph, float* s_out, float* c_out) {
    const float q  = fmaf(ph, 0.63661977236758134f, 12582912.0f); // rint(ph*2/pi)+magic
    const float qf = q - 12582912.0f;
    float x = fmaf(qf, -1.57079637050628662f, ph);   // ph - qf*PIO2_HI
    x = fmaf(qf, 4.37113900018624283e-8f, x);        // - qf*PIO2_LO
    const float x2 = x * x;
    // sin poly (odd, deg 7)
    float ps = fmaf(x2, -1.9841270e-4f, 8.3333310e-3f);
    ps = fmaf(x2, ps, -1.6666667e-1f);
    ps = fmaf(x2, ps, 1.0f);
    const float s = x * ps;
    // cos poly (even, deg 8)
    float pc = fmaf(x2, 2.4801587e-5f, -1.3888889e-3f);
    pc = fmaf(x2, pc, 4.1666668e-2f);
    pc = fmaf(x2, pc, -0.5f);
    const float c = fmaf(x2, pc, 1.0f);
    // quadrant fixup (ALU pipe): n = low bits of q's mantissa
    const unsigned qb = __float_as_uint(q);
    const bool swap = (qb & 1u);
    const unsigned sgn_s = (qb & 2u) << 30;
    const unsigned sgn_c = ((qb + 1u) & 2u) << 30;
    const float s1 = swap ? c : s;
    const float c1 = swap ? s : c;
    *s_out = __uint_as_float(__float_as_uint(s1) ^ sgn_s);
    *c_out = __uint_as_float(__float_as_uint(c1) ^ sgn_c);
}

__global__ __launch_bounds__(256, 2) void spatial_embedding_sym_kernel(
    const float* __restrict__ coords,          // (B, N, 3)
    const unsigned char* __restrict__ mask,    // (B, N) bool, 1 = padded
    float* __restrict__ out)                   // (B, N, 512), pre-zeroed
{
    __shared__ float4 shp[T * T];              // (r, ampA, ampB, -)
    __shared__ float sxi[T], syi[T], szi[T], svi[T];
    __shared__ float sxj[T], syj[T], szj[T], svj[T];

    const int strip = blockIdx.x;
    const int ti    = blockIdx.y;
    const int b     = blockIdx.z;
    const int tid   = threadIdx.x;             // wave index m

    const int tj_end = strip * W + W;
    if (tj_end <= ti) return;                  // strip entirely below diagonal
    const int tj_beg = (ti > strip * W) ? ti : strip * W;

    const float* cb = coords + (size_t)b * N_PTS * 3;
    const unsigned char* mb = mask + (size_t)b * N_PTS;

    // k_m = 2*pi / lam_m, lam = geomspace(2, 100, 256); double to match numpy
    const double tt = (double)tid / (double)(N_WAVES - 1);
    const float  k  = (float)(6.283185307179586 / (2.0 * pow(50.0, tt)));

    if (tid < T) {
        const int ig = ti * T + tid;
        sxi[tid] = cb[ig * 3 + 0];
        syi[tid] = cb[ig * 3 + 1];
        szi[tid] = cb[ig * 3 + 2];
        svi[tid] = (mb[ig] == 0) ? 1.0f : 0.0f;
    }

    // i-side accumulators persist across the whole strip
    float aiR[T], aiI[T];
    #pragma unroll
    for (int q = 0; q < T; ++q) { aiR[q] = 0.0f; aiI[q] = 0.0f; }

    for (int tj = tj_beg; tj < tj_end; ++tj) {
        __syncthreads();   // covers svi/sxi visibility and shp/j-array reuse
        if (tid < T) {
            const int jg = tj * T + tid;
            sxj[tid] = cb[jg * 3 + 0];
            syj[tid] = cb[jg * 3 + 1];
            szj[tid] = cb[jg * 3 + 2];
            svj[tid] = (mb[jg] == 0) ? 1.0f : 0.0f;
        }
        __syncthreads();

        // ---- Phase A: 256 threads build the 16x16 pair table ----
        {
            const int ii = tid >> 4;
            const int jj = tid & (T - 1);
            const float dx = sxi[ii] - sxj[jj];
            const float dy = syi[ii] - syj[jj];
            const float dz = szi[ii] - szj[jj];
            float sq = fmaf(dx, dx, fmaf(dy, dy, dz * dz));
            const bool self = (ti == tj) && (ii == jj);
            if (self) sq = 1.0f;                      // sq_safe
            const float rs = rsqrtf(sq);
            const float r  = sq * rs;
            const float ar = 0.07957747154594767f * rs;   // 1/(4*pi*r)
            const float ampA = (!self && svj[jj] != 0.0f) ? ar : 0.0f;
            const float ampB = (ti != tj && svi[ii] != 0.0f) ? ar : 0.0f;
            shp[tid] = make_float4(r, ampA, ampB, 0.0f);
        }
        __syncthreads();

        // ---- Phase B: each thread (wave m) sweeps 256 pairs ----
        float ajR[T], ajI[T];
        #pragma unroll
        for (int q = 0; q < T; ++q) { ajR[q] = 0.0f; ajI[q] = 0.0f; }

        // MUFU path: ii in [0, F_MUFU)
        #pragma unroll
        for (int ii = 0; ii < F_MUFU; ++ii) {
            #pragma unroll
            for (int jj = 0; jj < T; ++jj) {
                const float4 ra = shp[ii * T + jj];   // broadcast LDS.128
                const float ph = k * ra.x;
                const float s = __sinf(ph);
                const float c = __cosf(ph);
                aiR[ii] = fmaf(ra.y, c, aiR[ii]);
                aiI[ii] = fmaf(ra.y, s, aiI[ii]);
                ajR[jj] = fmaf(ra.z, c, ajR[jj]);
                ajI[jj] = fmaf(ra.z, s, ajI[jj]);
            }
        }
        // FMA-poly path: ii in [F_MUFU, T)
        #pragma unroll
        for (int ii = F_MUFU; ii < T; ++ii) {
            #pragma unroll
            for (int jj = 0; jj < T; ++jj) {
                const float4 ra = shp[ii * T + jj];
                float s, c;
                sincos_poly(k * ra.x, &s, &c);
                aiR[ii] = fmaf(ra.y, c, aiR[ii]);
                aiI[ii] = fmaf(ra.y, s, aiI[ii]);
                ajR[jj] = fmaf(ra.z, c, ajR[jj]);
                ajI[jj] = fmaf(ra.z, s, ajI[jj]);
            }
        }

        // flush j-side partials (skip diagonal tile: ampB was 0 there)
        if (tj != ti) {
            #pragma unroll
            for (int jj = 0; jj < T; ++jj) {
                const float v = svj[jj];              // target-row validity
                float* p = out + ((size_t)(b * N_PTS) + tj * T + jj) * (2 * N_WAVES)
                               + 2 * tid;
                red_add_v2(p, ajR[jj] * v, ajI[jj] * v);
            }
        }
    }

    // flush i-side partials once per block
    #pragma unroll
    for (int ii = 0; ii < T; ++ii) {
        const float v = svi[ii];                      // target-row validity
        float* p = out + ((size_t)(b * N_PTS) + ti * T + ii) * (2 * N_WAVES)
                       + 2 * tid;
        red_add_v2(p, aiR[ii] * v, aiI[ii] * v);
    }
}

extern "C" void kernel_launch(void* const* d_in, const int* in_sizes, int n_in,
                              void* d_out, int out_size)
{
    const float* coords       = (const float*)d_in[0];
    const unsigned char* mask = (const unsigned char*)d_in[1];
    float* out                = (float*)d_out;

    const int BN = in_sizes[1];        // B * N
    const int B  = BN / N_PTS;

    // output is accumulated atomically -> must start from zero
    cudaMemsetAsync(d_out, 0, (size_t)out_size * sizeof(float), 0);

    dim3 grid(NSTRIPS, NT, B);
    spatial_embedding_sym_kernel<<<grid, 256>>>(coords, mask, out);
}